// round 9
// baseline (speedup 1.0000x reference)
#include <cuda_runtime.h>
#include <cuda_fp16.h>
#include <math.h>

#define NMAX 100000
#define EMAX 1600000
#define CIN  64

// ---------------- device scratch (no allocation allowed) ----------------
__device__ int   g_is64;
__device__ int   g_src[EMAX];
__device__ int   g_dstE[EMAX];
__device__ int   g_esrc[EMAX];          // CSR: src ids sorted by dst
__device__ int   g_cnt[NMAX];
__device__ int   g_scan[NMAX];
__device__ int   g_bsum[512];
__device__ int   g_boff[512];
__device__ int   g_rowstart[NMAX + 1];
__device__ int   g_cur[NMAX];
__device__ float g_inv[NMAX];
__device__ __align__(256) __half g_ylh[(size_t)NMAX * 64];   // fp16 gather payload
__device__ __align__(256) float  g_yr[(size_t)NMAX * 64];
__device__ __align__(256) float  g_h0[(size_t)NMAX * 64];
__device__ __align__(256) float  g_h1[(size_t)NMAX * 64];
__device__ float g_stats[128];          // [sum(64) | sumsq(64)]
__device__ float g_aff0[128];           // [scale | shift]
__device__ float g_aff1[128];

// ---------------- packed f32x2 helpers ----------------
__device__ __forceinline__ unsigned long long pk2(float lo, float hi) {
    unsigned long long r;
    asm("mov.b64 %0, {%1, %2};" : "=l"(r) : "f"(lo), "f"(hi));
    return r;
}
__device__ __forceinline__ void upk2(unsigned long long v, float& lo, float& hi) {
    asm("mov.b64 {%0, %1}, %2;" : "=f"(lo), "=f"(hi) : "l"(v));
}
__device__ __forceinline__ void fma2(unsigned long long& d,
                                     unsigned long long a, unsigned long long b) {
    asm("fma.rn.f32x2 %0, %1, %2, %3;" : "=l"(d) : "l"(a), "l"(b), "l"(d));
}

// ---------------- dtype detection (int64 vs int32 edge_index) ----------------
__global__ void k_detect(const unsigned int* __restrict__ w) {
    int i = threadIdx.x;
    int ok = (w[2 * i + 1] == 0u) && (w[2 * (i + 1024) + 1] == 0u);
    int all = __syncthreads_and(ok);
    if (i == 0) g_is64 = all ? 1 : 0;
}

__global__ void k_zero_cnt(int N) {
    int i = blockIdx.x * blockDim.x + threadIdx.x;
    if (i < N) g_cnt[i] = 0;
}

__global__ void k_decode(const void* __restrict__ ei, int E) {
    int i = blockIdx.x * blockDim.x + threadIdx.x;
    if (i >= E) return;
    int s, d;
    if (g_is64) {
        const long long* p = (const long long*)ei;
        s = (int)p[i];
        d = (int)p[E + i];
    } else {
        const int* p = (const int*)ei;
        s = p[i];
        d = p[E + i];
    }
    g_src[i] = s;
    g_dstE[i] = d;
    atomicAdd(&g_cnt[d], 1);
}

__global__ void k_scan1(int N) {
    __shared__ int sh[256];
    int i = blockIdx.x * 256 + threadIdx.x;
    int v = (i < N) ? g_cnt[i] : 0;
    sh[threadIdx.x] = v;
    __syncthreads();
    for (int off = 1; off < 256; off <<= 1) {
        int t = (threadIdx.x >= off) ? sh[threadIdx.x - off] : 0;
        __syncthreads();
        sh[threadIdx.x] += t;
        __syncthreads();
    }
    if (i < N) g_scan[i] = sh[threadIdx.x] - v;
    if (threadIdx.x == 255) g_bsum[blockIdx.x] = sh[255];
}

__global__ void k_scan2(int NB) {
    __shared__ int sh[512];
    int i = threadIdx.x;
    int v = (i < NB) ? g_bsum[i] : 0;
    sh[i] = v;
    __syncthreads();
    for (int off = 1; off < 512; off <<= 1) {
        int t = (i >= off) ? sh[i - off] : 0;
        __syncthreads();
        sh[i] += t;
        __syncthreads();
    }
    g_boff[i] = sh[i] - v;
}

__global__ void k_scan3(int N, int E) {
    int i = blockIdx.x * blockDim.x + threadIdx.x;
    if (i < N) {
        int rs = g_scan[i] + g_boff[i >> 8];
        g_rowstart[i] = rs;
        g_cur[i] = rs;
        g_inv[i] = 1.0f / fmaxf((float)g_cnt[i], 1.0f);
    }
    if (i == N) g_rowstart[N] = E;
}

__global__ void k_fill(int E) {
    int i = blockIdx.x * blockDim.x + threadIdx.x;
    if (i >= E) return;
    int d = g_dstE[i];
    int pos = atomicAdd(&g_cur[d], 1);
    g_esrc[pos] = g_src[i];
}

// ---------------- linear: ylh = half(f(x)@Wl), yr = f(x)@Wr + b ----------------
// f = relu(aff-scale/shift) when AFFINE else identity.
// Combined weight matrix W = [Wl | Wr] of width 2*COUT staged in smem.
// 8 nodes x 1 channel-pair per thread; x vectorized float4 over k.
template <int COUT, bool AFFINE>
__global__ void __launch_bounds__((COUT / 2) * 8)
k_lin(const float* __restrict__ x,
      const float* __restrict__ aff,
      const float* __restrict__ Wl,
      const float* __restrict__ Wr,
      const float* __restrict__ bias,
      __half* __restrict__ ylh,
      float* __restrict__ yr,
      int N) {
    constexpr int W  = 2 * COUT;        // 128 or 80
    constexpr int CQ = W / 4;           // 32 or 20 channel-pair groups
    constexpr int NT = 64;              // node tile
    constexpr int THREADS = CQ * 8;     // 256 or 160
    constexpr int RS = CIN + 4;         // 68

    extern __shared__ float smem[];
    float* sX = smem;                   // NT*RS
    float* sW = sX + NT * RS;           // CIN*W

    int tid = threadIdx.x;
    // stage combined weights [k][0:COUT)=Wl row k, [COUT:W)=Wr row k
    for (int i = tid; i < CIN * W; i += THREADS) {
        int k = i / W;
        int c = i % W;
        sW[i] = (c < COUT) ? Wl[k * COUT + c] : Wr[k * COUT + (c - COUT)];
    }

    int tile = blockIdx.x * NT;
    for (int q = tid; q < NT * (CIN / 4); q += THREADS) {
        int row = q / (CIN / 4);
        int c4  = (q % (CIN / 4)) * 4;
        int n = tile + row;
        float4 xv = make_float4(0.f, 0.f, 0.f, 0.f);
        if (n < N) {
            xv = *reinterpret_cast<const float4*>(x + (size_t)n * CIN + c4);
            if (AFFINE) {
                float4 A = *reinterpret_cast<const float4*>(aff + c4);
                float4 B = *reinterpret_cast<const float4*>(aff + 64 + c4);
                xv.x = fmaxf(fmaf(xv.x, A.x, B.x), 0.f);
                xv.y = fmaxf(fmaf(xv.y, A.y, B.y), 0.f);
                xv.z = fmaxf(fmaf(xv.z, A.z, B.z), 0.f);
                xv.w = fmaxf(fmaf(xv.w, A.w, B.w), 0.f);
            }
        }
        *reinterpret_cast<float4*>(sX + row * RS + c4) = xv;
    }
    __syncthreads();

    int cg  = tid % CQ;                 // channel-pair group
    int nb  = (tid / CQ) * 8;           // node base (8 nodes per thread)
    int ch0 = 2 * cg;                   // output channel pair {ch0, ch0+1}

    unsigned long long acc0[8], acc1[8];    // Wl-product | Wr-product(+bias)
    {
        float2 b = *reinterpret_cast<const float2*>(bias + ch0);
        unsigned long long bp = pk2(b.x, b.y);
        unsigned long long zp = pk2(0.f, 0.f);
#pragma unroll
        for (int i = 0; i < 8; i++) { acc0[i] = zp; acc1[i] = bp; }
    }

    for (int k4 = 0; k4 < CIN; k4 += 4) {
        float4 xv[8];
#pragma unroll
        for (int i = 0; i < 8; i++)
            xv[i] = *reinterpret_cast<const float4*>(sX + (nb + i) * RS + k4);
#pragma unroll
        for (int kk = 0; kk < 4; kk++) {
            float2 w0 = *reinterpret_cast<const float2*>(sW + (k4 + kk) * W + ch0);
            float2 w1 = *reinterpret_cast<const float2*>(sW + (k4 + kk) * W + ch0 + COUT);
            unsigned long long w0p = pk2(w0.x, w0.y);
            unsigned long long w1p = pk2(w1.x, w1.y);
#pragma unroll
            for (int i = 0; i < 8; i++) {
                float xs = (kk == 0) ? xv[i].x : (kk == 1) ? xv[i].y
                         : (kk == 2) ? xv[i].z : xv[i].w;
                unsigned long long xp = pk2(xs, xs);
                fma2(acc0[i], xp, w0p);
                fma2(acc1[i], xp, w1p);
            }
        }
    }

#pragma unroll
    for (int i = 0; i < 8; i++) {
        int n = tile + nb + i;
        if (n < N) {
            float lo, hi;
            upk2(acc0[i], lo, hi);
            *reinterpret_cast<__half2*>(ylh + (size_t)n * COUT + ch0) =
                __floats2half2_rn(lo, hi);
            upk2(acc1[i], lo, hi);
            *reinterpret_cast<float2*>(yr + (size_t)n * COUT + ch0) =
                make_float2(lo, hi);
        }
    }
}

// ---------------- CSR gather reduce: out = invdeg * sum ylh[src] + yr ----------------
// CH = COUT/8 threads per node, each owns one 16B chunk (8 fp16 channels).
// Inner loop manually unrolled 4x: 4 index loads, then 4 independent gathers.
template <int COUT, bool STATS, int BLOCK>
__global__ void __launch_bounds__(BLOCK)
k_agg(const __half* __restrict__ ylh,
      const float* __restrict__ yrr,
      float* __restrict__ out,
      int N) {
    constexpr int CH = COUT / 8;

    __shared__ float sSum[64];
    __shared__ float sSq[64];
    int tid = threadIdx.x;
    if (STATS) {
        if (tid < 64) { sSum[tid] = 0.0f; sSq[tid] = 0.0f; }
        __syncthreads();
    }

    int t = blockIdx.x * BLOCK + tid;
    int n = t / CH;
    int c = (t % CH) * 8;
    bool active = (n < N);

    float r[8];
    if (active) {
        int beg = g_rowstart[n];
        int end = g_rowstart[n + 1];
        float a[8];
#pragma unroll
        for (int k = 0; k < 8; k++) a[k] = 0.0f;

        const __half* __restrict__ base = ylh + c;
        int j = beg;
        for (; j + 3 < end; j += 4) {
            int s0 = __ldg(&g_esrc[j + 0]);
            int s1 = __ldg(&g_esrc[j + 1]);
            int s2 = __ldg(&g_esrc[j + 2]);
            int s3 = __ldg(&g_esrc[j + 3]);
            uint4 v0 = *reinterpret_cast<const uint4*>(base + (size_t)s0 * COUT);
            uint4 v1 = *reinterpret_cast<const uint4*>(base + (size_t)s1 * COUT);
            uint4 v2 = *reinterpret_cast<const uint4*>(base + (size_t)s2 * COUT);
            uint4 v3 = *reinterpret_cast<const uint4*>(base + (size_t)s3 * COUT);
#pragma unroll
            for (int q = 0; q < 4; q++) {
                uint4 v = (q == 0) ? v0 : (q == 1) ? v1 : (q == 2) ? v2 : v3;
                float2 f0 = __half22float2(*reinterpret_cast<__half2*>(&v.x));
                float2 f1 = __half22float2(*reinterpret_cast<__half2*>(&v.y));
                float2 f2 = __half22float2(*reinterpret_cast<__half2*>(&v.z));
                float2 f3 = __half22float2(*reinterpret_cast<__half2*>(&v.w));
                a[0] += f0.x; a[1] += f0.y;
                a[2] += f1.x; a[3] += f1.y;
                a[4] += f2.x; a[5] += f2.y;
                a[6] += f3.x; a[7] += f3.y;
            }
        }
        for (; j < end; j++) {
            int s = __ldg(&g_esrc[j]);
            uint4 v = *reinterpret_cast<const uint4*>(base + (size_t)s * COUT);
            float2 f0 = __half22float2(*reinterpret_cast<__half2*>(&v.x));
            float2 f1 = __half22float2(*reinterpret_cast<__half2*>(&v.y));
            float2 f2 = __half22float2(*reinterpret_cast<__half2*>(&v.z));
            float2 f3 = __half22float2(*reinterpret_cast<__half2*>(&v.w));
            a[0] += f0.x; a[1] += f0.y;
            a[2] += f1.x; a[3] += f1.y;
            a[4] += f2.x; a[5] += f2.y;
            a[6] += f3.x; a[7] += f3.y;
        }

        float inv = g_inv[n];
        float4 b0 = *reinterpret_cast<const float4*>(yrr + (size_t)n * COUT + c);
        float4 b1 = *reinterpret_cast<const float4*>(yrr + (size_t)n * COUT + c + 4);
        r[0] = fmaf(a[0], inv, b0.x);
        r[1] = fmaf(a[1], inv, b0.y);
        r[2] = fmaf(a[2], inv, b0.z);
        r[3] = fmaf(a[3], inv, b0.w);
        r[4] = fmaf(a[4], inv, b1.x);
        r[5] = fmaf(a[5], inv, b1.y);
        r[6] = fmaf(a[6], inv, b1.z);
        r[7] = fmaf(a[7], inv, b1.w);
        *reinterpret_cast<float4*>(out + (size_t)n * COUT + c) =
            make_float4(r[0], r[1], r[2], r[3]);
        *reinterpret_cast<float4*>(out + (size_t)n * COUT + c + 4) =
            make_float4(r[4], r[5], r[6], r[7]);
    }

    if (STATS) {
        if (active) {
#pragma unroll
            for (int k = 0; k < 8; k++) {
                atomicAdd(&sSum[c + k], r[k]);
                atomicAdd(&sSq[c + k],  r[k] * r[k]);
            }
        }
        __syncthreads();
        if (tid < 64) {
            atomicAdd(&g_stats[tid],      sSum[tid]);
            atomicAdd(&g_stats[64 + tid], sSq[tid]);
        }
    }
}

__global__ void k_zero_stats() {
    int i = threadIdx.x;
    if (i < 128) g_stats[i] = 0.0f;
}

__global__ void k_bn_finalize(const float* __restrict__ g, const float* __restrict__ be,
                              float invN, float* __restrict__ aff) {
    int c = threadIdx.x;
    if (c < 64) {
        float mu  = g_stats[c] * invN;
        float var = g_stats[64 + c] * invN - mu * mu;
        float a = g[c] * rsqrtf(var + 1e-5f);
        aff[c] = a;
        aff[64 + c] = be[c] - mu * a;
    }
}

// ---------------- launch ----------------
extern "C" void kernel_launch(void* const* d_in, const int* in_sizes, int n_in,
                              void* d_out, int out_size) {
    const float* x   = (const float*)d_in[0];
    const void*  ei  = d_in[1];
    const float* Wl0 = (const float*)d_in[2];
    const float* Wr0 = (const float*)d_in[3];
    const float* b0  = (const float*)d_in[4];
    const float* Wl1 = (const float*)d_in[5];
    const float* Wr1 = (const float*)d_in[6];
    const float* b1  = (const float*)d_in[7];
    const float* Wl2 = (const float*)d_in[8];
    const float* Wr2 = (const float*)d_in[9];
    const float* b2  = (const float*)d_in[10];
    const float* g0  = (const float*)d_in[11];
    const float* be0 = (const float*)d_in[12];
    const float* g1  = (const float*)d_in[13];
    const float* be1 = (const float*)d_in[14];
    float* out = (float*)d_out;

    int N = in_sizes[0] / 64;
    int E = in_sizes[1] / 2;
    float invN = 1.0f / (float)N;

    __half* ylhp;
    float *yrp, *h0p, *h1p, *aff0p, *aff1p;
    cudaGetSymbolAddress((void**)&ylhp, g_ylh);
    cudaGetSymbolAddress((void**)&yrp, g_yr);
    cudaGetSymbolAddress((void**)&h0p, g_h0);
    cudaGetSymbolAddress((void**)&h1p, g_h1);
    cudaGetSymbolAddress((void**)&aff0p, g_aff0);
    cudaGetSymbolAddress((void**)&aff1p, g_aff1);

    const int smem64 = (64 * (CIN + 4) + CIN * 128) * 4;
    const int smem40 = (64 * (CIN + 4) + CIN * 80) * 4;
    cudaFuncSetAttribute(k_lin<64, false>,
                         cudaFuncAttributeMaxDynamicSharedMemorySize, smem64);
    cudaFuncSetAttribute(k_lin<64, true>,
                         cudaFuncAttributeMaxDynamicSharedMemorySize, smem64);
    cudaFuncSetAttribute(k_lin<40, true>,
                         cudaFuncAttributeMaxDynamicSharedMemorySize, smem40);

    const int nodeBlocks  = (N + 255) / 256;
    const int nodeBlocks1 = (N + 256) / 256;
    const int edgeBlocks  = (E + 255) / 256;
    const int NB          = (N + 255) / 256;
    const int agg64Blocks = (N * 8 + 255) / 256;
    const int agg40Blocks = (N * 5 + 319) / 320;
    const int mmGrid      = (N + 63) / 64;

    // ---- CSR build (round-8 structure preserved; lin0 at index 3 for ncu) ----
    k_detect<<<1, 1024>>>((const unsigned int*)ei);
    k_zero_cnt<<<nodeBlocks, 256>>>(N);
    k_decode<<<edgeBlocks, 256>>>(ei, E);
    k_lin<64, false><<<mmGrid, 256, smem64>>>(x, nullptr, Wl0, Wr0, b0, ylhp, yrp, N);
    k_scan1<<<NB, 256>>>(N);
    k_scan2<<<1, 512>>>(NB);
    k_scan3<<<nodeBlocks1, 256>>>(N, E);
    k_fill<<<edgeBlocks, 256>>>(E);

    // ---- layer 0 ----
    k_zero_stats<<<1, 128>>>();
    k_agg<64, true, 256><<<agg64Blocks, 256>>>(ylhp, yrp, h0p, N);
    k_bn_finalize<<<1, 64>>>(g0, be0, invN, aff0p);

    // ---- layer 1 ----
    k_lin<64, true><<<mmGrid, 256, smem64>>>(h0p, aff0p, Wl1, Wr1, b1, ylhp, yrp, N);
    k_zero_stats<<<1, 128>>>();
    k_agg<64, true, 256><<<agg64Blocks, 256>>>(ylhp, yrp, h1p, N);
    k_bn_finalize<<<1, 64>>>(g1, be1, invN, aff1p);

    // ---- layer 2 ----
    k_lin<40, true><<<mmGrid, 160, smem40>>>(h1p, aff1p, Wl2, Wr2, b2, ylhp, yrp, N);
    k_agg<40, false, 320><<<agg40Blocks, 320>>>(ylhp, yrp, out, N);
}

// round 10
// speedup vs baseline: 1.0448x; 1.0448x over previous
#include <cuda_runtime.h>
#include <cuda_fp16.h>
#include <math.h>

#define NMAX 100000
#define EMAX 1600000
#define CIN  64

// ---------------- device scratch (no allocation allowed) ----------------
__device__ int   g_is64;
__device__ int   g_src[EMAX];
__device__ int   g_dstE[EMAX];
__device__ int   g_esrc[EMAX];          // CSR: src ids sorted by dst
__device__ int   g_cnt[NMAX];
__device__ int   g_scan[NMAX];
__device__ int   g_bsum[512];
__device__ int   g_boff[512];
__device__ int   g_rowstart[NMAX + 1];
__device__ int   g_cur[NMAX];
__device__ float g_inv[NMAX];
__device__ __align__(256) __half g_ylh[(size_t)NMAX * 64];   // fp16 gather payload
__device__ __align__(256) float  g_yr[(size_t)NMAX * 64];
__device__ __align__(256) float  g_h0[(size_t)NMAX * 64];
__device__ __align__(256) float  g_h1[(size_t)NMAX * 64];
__device__ float g_stats0[128];         // layer0 [sum(64) | sumsq(64)]
__device__ float g_stats1[128];         // layer1
__device__ float g_aff0[128];           // [scale | shift]
__device__ float g_aff1[128];

// ---------------- packed f32x2 helpers ----------------
__device__ __forceinline__ unsigned long long pk2(float lo, float hi) {
    unsigned long long r;
    asm("mov.b64 %0, {%1, %2};" : "=l"(r) : "f"(lo), "f"(hi));
    return r;
}
__device__ __forceinline__ void upk2(unsigned long long v, float& lo, float& hi) {
    asm("mov.b64 {%0, %1}, %2;" : "=f"(lo), "=f"(hi) : "l"(v));
}
__device__ __forceinline__ void fma2(unsigned long long& d,
                                     unsigned long long a, unsigned long long b) {
    asm("fma.rn.f32x2 %0, %1, %2, %3;" : "=l"(d) : "l"(a), "l"(b), "l"(d));
}

// ---------------- dtype detection (int64 vs int32 edge_index) ----------------
__global__ void k_detect(const unsigned int* __restrict__ w) {
    int i = threadIdx.x;
    int ok = (w[2 * i + 1] == 0u) && (w[2 * (i + 1024) + 1] == 0u);
    int all = __syncthreads_and(ok);
    if (i == 0) g_is64 = all ? 1 : 0;
}

__global__ void k_zero_cnt(int N) {
    int i = blockIdx.x * blockDim.x + threadIdx.x;
    if (i < N) g_cnt[i] = 0;
}

__global__ void k_zero_stats2() {
    int i = threadIdx.x;
    if (i < 128) { g_stats0[i] = 0.0f; g_stats1[i] = 0.0f; }
}

__global__ void k_decode(const void* __restrict__ ei, int E) {
    int i = blockIdx.x * blockDim.x + threadIdx.x;
    if (i >= E) return;
    int s, d;
    if (g_is64) {
        const long long* p = (const long long*)ei;
        s = (int)p[i];
        d = (int)p[E + i];
    } else {
        const int* p = (const int*)ei;
        s = p[i];
        d = p[E + i];
    }
    g_src[i] = s;
    g_dstE[i] = d;
    atomicAdd(&g_cnt[d], 1);
}

__global__ void k_scan1(int N) {
    __shared__ int sh[256];
    int i = blockIdx.x * 256 + threadIdx.x;
    int v = (i < N) ? g_cnt[i] : 0;
    sh[threadIdx.x] = v;
    __syncthreads();
    for (int off = 1; off < 256; off <<= 1) {
        int t = (threadIdx.x >= off) ? sh[threadIdx.x - off] : 0;
        __syncthreads();
        sh[threadIdx.x] += t;
        __syncthreads();
    }
    if (i < N) g_scan[i] = sh[threadIdx.x] - v;
    if (threadIdx.x == 255) g_bsum[blockIdx.x] = sh[255];
}

__global__ void k_scan2(int NB) {
    __shared__ int sh[512];
    int i = threadIdx.x;
    int v = (i < NB) ? g_bsum[i] : 0;
    sh[i] = v;
    __syncthreads();
    for (int off = 1; off < 512; off <<= 1) {
        int t = (i >= off) ? sh[i - off] : 0;
        __syncthreads();
        sh[i] += t;
        __syncthreads();
    }
    g_boff[i] = sh[i] - v;
}

__global__ void k_scan3(int N, int E) {
    int i = blockIdx.x * blockDim.x + threadIdx.x;
    if (i < N) {
        int rs = g_scan[i] + g_boff[i >> 8];
        g_rowstart[i] = rs;
        g_cur[i] = rs;
        g_inv[i] = 1.0f / fmaxf((float)g_cnt[i], 1.0f);
    }
    if (i == N) g_rowstart[N] = E;
}

__global__ void k_fill(int E) {
    int i = blockIdx.x * blockDim.x + threadIdx.x;
    if (i >= E) return;
    int d = g_dstE[i];
    int pos = atomicAdd(&g_cur[d], 1);
    g_esrc[pos] = g_src[i];
}

// ---------------- linear: ylh = half(f(x)@Wl), yr = f(x)@Wr + b ----------------
// f = relu(aff-scale/shift) when AFFINE else identity. (identical to round 8)
template <int COUT, bool AFFINE>
__global__ void __launch_bounds__((COUT / 2) * 8)
k_lin(const float* __restrict__ x,
      const float* __restrict__ aff,
      const float* __restrict__ Wl,
      const float* __restrict__ Wr,
      const float* __restrict__ bias,
      __half* __restrict__ ylh,
      float* __restrict__ yr,
      int N) {
    constexpr int W  = 2 * COUT;
    constexpr int CQ = W / 4;
    constexpr int NT = 64;
    constexpr int THREADS = CQ * 8;
    constexpr int RS = CIN + 4;

    extern __shared__ float smem[];
    float* sX = smem;                   // NT*RS
    float* sW = sX + NT * RS;           // CIN*W

    int tid = threadIdx.x;
    for (int i = tid; i < CIN * W; i += THREADS) {
        int k = i / W;
        int c = i % W;
        sW[i] = (c < COUT) ? Wl[k * COUT + c] : Wr[k * COUT + (c - COUT)];
    }

    int tile = blockIdx.x * NT;
    for (int q = tid; q < NT * (CIN / 4); q += THREADS) {
        int row = q / (CIN / 4);
        int c4  = (q % (CIN / 4)) * 4;
        int n = tile + row;
        float4 xv = make_float4(0.f, 0.f, 0.f, 0.f);
        if (n < N) {
            xv = *reinterpret_cast<const float4*>(x + (size_t)n * CIN + c4);
            if (AFFINE) {
                float4 A = *reinterpret_cast<const float4*>(aff + c4);
                float4 B = *reinterpret_cast<const float4*>(aff + 64 + c4);
                xv.x = fmaxf(fmaf(xv.x, A.x, B.x), 0.f);
                xv.y = fmaxf(fmaf(xv.y, A.y, B.y), 0.f);
                xv.z = fmaxf(fmaf(xv.z, A.z, B.z), 0.f);
                xv.w = fmaxf(fmaf(xv.w, A.w, B.w), 0.f);
            }
        }
        *reinterpret_cast<float4*>(sX + row * RS + c4) = xv;
    }
    __syncthreads();

    int cg  = tid % CQ;
    int nb  = (tid / CQ) * 8;
    int ch0 = 2 * cg;

    unsigned long long acc0[8], acc1[8];
    {
        float2 b = *reinterpret_cast<const float2*>(bias + ch0);
        unsigned long long bp = pk2(b.x, b.y);
        unsigned long long zp = pk2(0.f, 0.f);
#pragma unroll
        for (int i = 0; i < 8; i++) { acc0[i] = zp; acc1[i] = bp; }
    }

    for (int k4 = 0; k4 < CIN; k4 += 4) {
        float4 xv[8];
#pragma unroll
        for (int i = 0; i < 8; i++)
            xv[i] = *reinterpret_cast<const float4*>(sX + (nb + i) * RS + k4);
#pragma unroll
        for (int kk = 0; kk < 4; kk++) {
            float2 w0 = *reinterpret_cast<const float2*>(sW + (k4 + kk) * W + ch0);
            float2 w1 = *reinterpret_cast<const float2*>(sW + (k4 + kk) * W + ch0 + COUT);
            unsigned long long w0p = pk2(w0.x, w0.y);
            unsigned long long w1p = pk2(w1.x, w1.y);
#pragma unroll
            for (int i = 0; i < 8; i++) {
                float xs = (kk == 0) ? xv[i].x : (kk == 1) ? xv[i].y
                         : (kk == 2) ? xv[i].z : xv[i].w;
                unsigned long long xp = pk2(xs, xs);
                fma2(acc0[i], xp, w0p);
                fma2(acc1[i], xp, w1p);
            }
        }
    }

#pragma unroll
    for (int i = 0; i < 8; i++) {
        int n = tile + nb + i;
        if (n < N) {
            float lo, hi;
            upk2(acc0[i], lo, hi);
            *reinterpret_cast<__half2*>(ylh + (size_t)n * COUT + ch0) =
                __floats2half2_rn(lo, hi);
            upk2(acc1[i], lo, hi);
            *reinterpret_cast<float2*>(yr + (size_t)n * COUT + ch0) =
                make_float2(lo, hi);
        }
    }
}

// ---------------- CSR gather reduce: out = invdeg * sum ylh[src] + yr ----------------
// (round-8 body; stats buffer passed as parameter for ping-pong)
template <int COUT, bool STATS, int BLOCK>
__global__ void __launch_bounds__(BLOCK)
k_agg(const __half* __restrict__ ylh,
      const float* __restrict__ yrr,
      float* __restrict__ out,
      float* __restrict__ stats,
      int N) {
    constexpr int CH = COUT / 8;

    __shared__ float sSum[64];
    __shared__ float sSq[64];
    int tid = threadIdx.x;
    if (STATS) {
        if (tid < 64) { sSum[tid] = 0.0f; sSq[tid] = 0.0f; }
        __syncthreads();
    }

    int t = blockIdx.x * BLOCK + tid;
    int n = t / CH;
    int c = (t % CH) * 8;
    bool active = (n < N);

    float r[8];
    if (active) {
        int beg = g_rowstart[n];
        int end = g_rowstart[n + 1];
        float2 a0 = make_float2(0.f, 0.f), a1 = a0, a2 = a0, a3 = a0;
#pragma unroll 2
        for (int j = beg; j < end; j++) {
            int s = __ldg(&g_esrc[j]);
            uint4 v = *reinterpret_cast<const uint4*>(ylh + (size_t)s * COUT + c);
            float2 f0 = __half22float2(*reinterpret_cast<__half2*>(&v.x));
            float2 f1 = __half22float2(*reinterpret_cast<__half2*>(&v.y));
            float2 f2 = __half22float2(*reinterpret_cast<__half2*>(&v.z));
            float2 f3 = __half22float2(*reinterpret_cast<__half2*>(&v.w));
            a0.x += f0.x; a0.y += f0.y;
            a1.x += f1.x; a1.y += f1.y;
            a2.x += f2.x; a2.y += f2.y;
            a3.x += f3.x; a3.y += f3.y;
        }
        float inv = g_inv[n];
        float4 b0 = *reinterpret_cast<const float4*>(yrr + (size_t)n * COUT + c);
        float4 b1 = *reinterpret_cast<const float4*>(yrr + (size_t)n * COUT + c + 4);
        r[0] = fmaf(a0.x, inv, b0.x);
        r[1] = fmaf(a0.y, inv, b0.y);
        r[2] = fmaf(a1.x, inv, b0.z);
        r[3] = fmaf(a1.y, inv, b0.w);
        r[4] = fmaf(a2.x, inv, b1.x);
        r[5] = fmaf(a2.y, inv, b1.y);
        r[6] = fmaf(a3.x, inv, b1.z);
        r[7] = fmaf(a3.y, inv, b1.w);
        *reinterpret_cast<float4*>(out + (size_t)n * COUT + c) =
            make_float4(r[0], r[1], r[2], r[3]);
        *reinterpret_cast<float4*>(out + (size_t)n * COUT + c + 4) =
            make_float4(r[4], r[5], r[6], r[7]);
    }

    if (STATS) {
        if (active) {
#pragma unroll
            for (int k = 0; k < 8; k++) {
                atomicAdd(&sSum[c + k], r[k]);
                atomicAdd(&sSq[c + k],  r[k] * r[k]);
            }
        }
        __syncthreads();
        if (tid < 64) {
            atomicAdd(&stats[tid],      sSum[tid]);
            atomicAdd(&stats[64 + tid], sSq[tid]);
        }
    }
}

__global__ void k_bn_finalize(const float* __restrict__ g, const float* __restrict__ be,
                              float invN, float* __restrict__ aff,
                              const float* __restrict__ stats) {
    int c = threadIdx.x;
    if (c < 64) {
        float mu  = stats[c] * invN;
        float var = stats[64 + c] * invN - mu * mu;
        float a = g[c] * rsqrtf(var + 1e-5f);
        aff[c] = a;
        aff[64 + c] = be[c] - mu * a;
    }
}

// ---------------- launch ----------------
extern "C" void kernel_launch(void* const* d_in, const int* in_sizes, int n_in,
                              void* d_out, int out_size) {
    const float* x   = (const float*)d_in[0];
    const void*  ei  = d_in[1];
    const float* Wl0 = (const float*)d_in[2];
    const float* Wr0 = (const float*)d_in[3];
    const float* b0  = (const float*)d_in[4];
    const float* Wl1 = (const float*)d_in[5];
    const float* Wr1 = (const float*)d_in[6];
    const float* b1  = (const float*)d_in[7];
    const float* Wl2 = (const float*)d_in[8];
    const float* Wr2 = (const float*)d_in[9];
    const float* b2  = (const float*)d_in[10];
    const float* g0  = (const float*)d_in[11];
    const float* be0 = (const float*)d_in[12];
    const float* g1  = (const float*)d_in[13];
    const float* be1 = (const float*)d_in[14];
    float* out = (float*)d_out;

    int N = in_sizes[0] / 64;
    int E = in_sizes[1] / 2;
    float invN = 1.0f / (float)N;

    __half* ylhp;
    float *yrp, *h0p, *h1p, *aff0p, *aff1p, *st0p, *st1p;
    cudaGetSymbolAddress((void**)&ylhp, g_ylh);
    cudaGetSymbolAddress((void**)&yrp, g_yr);
    cudaGetSymbolAddress((void**)&h0p, g_h0);
    cudaGetSymbolAddress((void**)&h1p, g_h1);
    cudaGetSymbolAddress((void**)&aff0p, g_aff0);
    cudaGetSymbolAddress((void**)&aff1p, g_aff1);
    cudaGetSymbolAddress((void**)&st0p, g_stats0);
    cudaGetSymbolAddress((void**)&st1p, g_stats1);

    const int smem64 = (64 * (CIN + 4) + CIN * 128) * 4;
    const int smem40 = (64 * (CIN + 4) + CIN * 80) * 4;
    cudaFuncSetAttribute(k_lin<64, false>,
                         cudaFuncAttributeMaxDynamicSharedMemorySize, smem64);
    cudaFuncSetAttribute(k_lin<64, true>,
                         cudaFuncAttributeMaxDynamicSharedMemorySize, smem64);
    cudaFuncSetAttribute(k_lin<40, true>,
                         cudaFuncAttributeMaxDynamicSharedMemorySize, smem40);

    // side stream + events, created once on the (uncaptured) correctness call;
    // host-side objects only — no device memory involved. Same launches every call.
    static cudaStream_t s2 = nullptr;
    static cudaEvent_t evFork = nullptr, evJoin = nullptr;
    if (s2 == nullptr) {
        cudaStreamCreateWithFlags(&s2, cudaStreamNonBlocking);
        cudaEventCreateWithFlags(&evFork, cudaEventDisableTiming);
        cudaEventCreateWithFlags(&evJoin, cudaEventDisableTiming);
    }

    const int nodeBlocks  = (N + 255) / 256;
    const int nodeBlocks1 = (N + 256) / 256;
    const int edgeBlocks  = (E + 255) / 256;
    const int NB          = (N + 255) / 256;
    const int agg64Blocks = (N * 8 + 255) / 256;
    const int agg40Blocks = (N * 5 + 319) / 320;
    const int mmGrid      = (N + 63) / 64;

    // ---- fork: lin0 + stats zero run concurrently with the CSR build ----
    cudaEventRecord(evFork, 0);
    cudaStreamWaitEvent(s2, evFork, 0);
    k_lin<64, false><<<mmGrid, 256, smem64, s2>>>(x, nullptr, Wl0, Wr0, b0,
                                                  ylhp, yrp, N);
    k_zero_stats2<<<1, 128, 0, s2>>>();
    cudaEventRecord(evJoin, s2);

    // ---- main stream: CSR build ----
    k_detect<<<1, 1024>>>((const unsigned int*)ei);
    k_zero_cnt<<<nodeBlocks, 256>>>(N);
    k_decode<<<edgeBlocks, 256>>>(ei, E);
    k_scan1<<<NB, 256>>>(N);
    k_scan2<<<1, 512>>>(NB);
    k_scan3<<<nodeBlocks1, 256>>>(N, E);
    k_fill<<<edgeBlocks, 256>>>(E);

    // ---- join, then the serial layer pipeline ----
    cudaStreamWaitEvent(0, evJoin, 0);

    // layer 0
    k_agg<64, true, 256><<<agg64Blocks, 256>>>(ylhp, yrp, h0p, st0p, N);
    k_bn_finalize<<<1, 64>>>(g0, be0, invN, aff0p, st0p);

    // layer 1
    k_lin<64, true><<<mmGrid, 256, smem64>>>(h0p, aff0p, Wl1, Wr1, b1, ylhp, yrp, N);
    k_agg<64, true, 256><<<agg64Blocks, 256>>>(ylhp, yrp, h1p, st1p, N);
    k_bn_finalize<<<1, 64>>>(g1, be1, invN, aff1p, st1p);

    // layer 2
    k_lin<40, true><<<mmGrid, 160, smem40>>>(h1p, aff1p, Wl2, Wr2, b2, ylhp, yrp, N);
    k_agg<40, false, 320><<<agg40Blocks, 320>>>(ylhp, yrp, out, nullptr, N);
}

// round 11
// speedup vs baseline: 1.2736x; 1.2190x over previous
#include <cuda_runtime.h>
#include <cuda_fp16.h>
#include <math.h>

#define NMAX 100000
#define EMAX 1600000
#define CIN  64

// ---------------- device scratch (no allocation allowed) ----------------
__device__ int   g_is64;
__device__ int   g_src[EMAX];
__device__ int   g_dstE[EMAX];
__device__ int   g_esrc[EMAX];          // CSR: src ids sorted by dst
__device__ int   g_cnt[NMAX];
__device__ int   g_scan[NMAX];
__device__ int   g_bsum[512];
__device__ int   g_boff[512];
__device__ int   g_rowstart[NMAX + 1];
__device__ int   g_cur[NMAX];
__device__ float g_inv[NMAX];
__device__ __align__(256) __half g_ylh[(size_t)NMAX * 64];   // fp16 gather payload
__device__ __align__(256) float  g_yr[(size_t)NMAX * 64];
__device__ __align__(256) float  g_h0[(size_t)NMAX * 64];
__device__ __align__(256) float  g_h1[(size_t)NMAX * 64];
__device__ float g_stats0[128];         // layer0 [sum(64) | sumsq(64)]
__device__ float g_stats1[128];         // layer1
__device__ int   g_arr0;                // arrival counters (last-block bn finalize)
__device__ int   g_arr1;
__device__ float g_aff0[128];           // [scale | shift]
__device__ float g_aff1[128];

// ---------------- packed f32x2 helpers ----------------
__device__ __forceinline__ unsigned long long pk2(float lo, float hi) {
    unsigned long long r;
    asm("mov.b64 %0, {%1, %2};" : "=l"(r) : "f"(lo), "f"(hi));
    return r;
}
__device__ __forceinline__ void upk2(unsigned long long v, float& lo, float& hi) {
    asm("mov.b64 {%0, %1}, %2;" : "=f"(lo), "=f"(hi) : "l"(v));
}
__device__ __forceinline__ void fma2(unsigned long long& d,
                                     unsigned long long a, unsigned long long b) {
    asm("fma.rn.f32x2 %0, %1, %2, %3;" : "=l"(d) : "l"(a), "l"(b), "l"(d));
}

// ---------------- dtype detection (int64 vs int32 edge_index) ----------------
__global__ void k_detect(const unsigned int* __restrict__ w) {
    int i = threadIdx.x;
    int ok = (w[2 * i + 1] == 0u) && (w[2 * (i + 1024) + 1] == 0u);
    int all = __syncthreads_and(ok);
    if (i == 0) g_is64 = all ? 1 : 0;
}

__global__ void k_zero_cnt(int N) {
    int i = blockIdx.x * blockDim.x + threadIdx.x;
    if (i < N) g_cnt[i] = 0;
}

__global__ void k_zero_stats2() {
    int i = threadIdx.x;
    if (i < 128) { g_stats0[i] = 0.0f; g_stats1[i] = 0.0f; }
    if (i == 0) { g_arr0 = 0; g_arr1 = 0; }
}

__global__ void k_decode(const void* __restrict__ ei, int E) {
    int i = blockIdx.x * blockDim.x + threadIdx.x;
    if (i >= E) return;
    int s, d;
    if (g_is64) {
        const long long* p = (const long long*)ei;
        s = (int)p[i];
        d = (int)p[E + i];
    } else {
        const int* p = (const int*)ei;
        s = p[i];
        d = p[E + i];
    }
    g_src[i] = s;
    g_dstE[i] = d;
    atomicAdd(&g_cnt[d], 1);
}

__global__ void k_scan1(int N) {
    __shared__ int sh[256];
    int i = blockIdx.x * 256 + threadIdx.x;
    int v = (i < N) ? g_cnt[i] : 0;
    sh[threadIdx.x] = v;
    __syncthreads();
    for (int off = 1; off < 256; off <<= 1) {
        int t = (threadIdx.x >= off) ? sh[threadIdx.x - off] : 0;
        __syncthreads();
        sh[threadIdx.x] += t;
        __syncthreads();
    }
    if (i < N) g_scan[i] = sh[threadIdx.x] - v;
    if (threadIdx.x == 255) g_bsum[blockIdx.x] = sh[255];
}

__global__ void k_scan2(int NB) {
    __shared__ int sh[512];
    int i = threadIdx.x;
    int v = (i < NB) ? g_bsum[i] : 0;
    sh[i] = v;
    __syncthreads();
    for (int off = 1; off < 512; off <<= 1) {
        int t = (i >= off) ? sh[i - off] : 0;
        __syncthreads();
        sh[i] += t;
        __syncthreads();
    }
    g_boff[i] = sh[i] - v;
}

__global__ void k_scan3(int N, int E) {
    int i = blockIdx.x * blockDim.x + threadIdx.x;
    if (i < N) {
        int rs = g_scan[i] + g_boff[i >> 8];
        g_rowstart[i] = rs;
        g_cur[i] = rs;
        g_inv[i] = 1.0f / fmaxf((float)g_cnt[i], 1.0f);
    }
    if (i == N) g_rowstart[N] = E;
}

__global__ void k_fill(int E) {
    int i = blockIdx.x * blockDim.x + threadIdx.x;
    if (i >= E) return;
    int d = g_dstE[i];
    int pos = atomicAdd(&g_cur[d], 1);
    g_esrc[pos] = g_src[i];
}

// ---------------- linear: ylh = half(f(x)@Wl), yr = f(x)@Wr + b ----------------
// f = relu(aff-scale/shift) when AFFINE else identity. (identical to round 10)
template <int COUT, bool AFFINE>
__global__ void __launch_bounds__((COUT / 2) * 8)
k_lin(const float* __restrict__ x,
      const float* __restrict__ aff,
      const float* __restrict__ Wl,
      const float* __restrict__ Wr,
      const float* __restrict__ bias,
      __half* __restrict__ ylh,
      float* __restrict__ yr,
      int N) {
    constexpr int W  = 2 * COUT;
    constexpr int CQ = W / 4;
    constexpr int NT = 64;
    constexpr int THREADS = CQ * 8;
    constexpr int RS = CIN + 4;

    extern __shared__ float smem[];
    float* sX = smem;                   // NT*RS
    float* sW = sX + NT * RS;           // CIN*W

    int tid = threadIdx.x;
    for (int i = tid; i < CIN * W; i += THREADS) {
        int k = i / W;
        int c = i % W;
        sW[i] = (c < COUT) ? Wl[k * COUT + c] : Wr[k * COUT + (c - COUT)];
    }

    int tile = blockIdx.x * NT;
    for (int q = tid; q < NT * (CIN / 4); q += THREADS) {
        int row = q / (CIN / 4);
        int c4  = (q % (CIN / 4)) * 4;
        int n = tile + row;
        float4 xv = make_float4(0.f, 0.f, 0.f, 0.f);
        if (n < N) {
            xv = *reinterpret_cast<const float4*>(x + (size_t)n * CIN + c4);
            if (AFFINE) {
                float4 A = *reinterpret_cast<const float4*>(aff + c4);
                float4 B = *reinterpret_cast<const float4*>(aff + 64 + c4);
                xv.x = fmaxf(fmaf(xv.x, A.x, B.x), 0.f);
                xv.y = fmaxf(fmaf(xv.y, A.y, B.y), 0.f);
                xv.z = fmaxf(fmaf(xv.z, A.z, B.z), 0.f);
                xv.w = fmaxf(fmaf(xv.w, A.w, B.w), 0.f);
            }
        }
        *reinterpret_cast<float4*>(sX + row * RS + c4) = xv;
    }
    __syncthreads();

    int cg  = tid % CQ;
    int nb  = (tid / CQ) * 8;
    int ch0 = 2 * cg;

    unsigned long long acc0[8], acc1[8];
    {
        float2 b = *reinterpret_cast<const float2*>(bias + ch0);
        unsigned long long bp = pk2(b.x, b.y);
        unsigned long long zp = pk2(0.f, 0.f);
#pragma unroll
        for (int i = 0; i < 8; i++) { acc0[i] = zp; acc1[i] = bp; }
    }

    for (int k4 = 0; k4 < CIN; k4 += 4) {
        float4 xv[8];
#pragma unroll
        for (int i = 0; i < 8; i++)
            xv[i] = *reinterpret_cast<const float4*>(sX + (nb + i) * RS + k4);
#pragma unroll
        for (int kk = 0; kk < 4; kk++) {
            float2 w0 = *reinterpret_cast<const float2*>(sW + (k4 + kk) * W + ch0);
            float2 w1 = *reinterpret_cast<const float2*>(sW + (k4 + kk) * W + ch0 + COUT);
            unsigned long long w0p = pk2(w0.x, w0.y);
            unsigned long long w1p = pk2(w1.x, w1.y);
#pragma unroll
            for (int i = 0; i < 8; i++) {
                float xs = (kk == 0) ? xv[i].x : (kk == 1) ? xv[i].y
                         : (kk == 2) ? xv[i].z : xv[i].w;
                unsigned long long xp = pk2(xs, xs);
                fma2(acc0[i], xp, w0p);
                fma2(acc1[i], xp, w1p);
            }
        }
    }

#pragma unroll
    for (int i = 0; i < 8; i++) {
        int n = tile + nb + i;
        if (n < N) {
            float lo, hi;
            upk2(acc0[i], lo, hi);
            *reinterpret_cast<__half2*>(ylh + (size_t)n * COUT + ch0) =
                __floats2half2_rn(lo, hi);
            upk2(acc1[i], lo, hi);
            *reinterpret_cast<float2*>(yr + (size_t)n * COUT + ch0) =
                make_float2(lo, hi);
        }
    }
}

// ---------------- CSR gather reduce: out = invdeg * sum ylh[src] + yr ----------------
// STATS epilogue: shfl-reduce across the 4 node-groups of the warp (stride 8,16),
// then conflict-free shared atomics from lanes 0-7 only. The LAST block (global
// arrival counter) computes the BN affine, replacing k_bn_finalize.
template <int COUT, bool STATS, int BLOCK>
__global__ void __launch_bounds__(BLOCK)
k_agg(const __half* __restrict__ ylh,
      const float* __restrict__ yrr,
      float* __restrict__ out,
      float* __restrict__ stats,
      int* __restrict__ arrive,
      const float* __restrict__ gamma,
      const float* __restrict__ beta,
      float* __restrict__ aff,
      float invN,
      int N) {
    constexpr int CH = COUT / 8;

    __shared__ float sSum[64];
    __shared__ float sSq[64];
    __shared__ int sLast;
    int tid = threadIdx.x;
    if (STATS) {
        if (tid < 64) { sSum[tid] = 0.0f; sSq[tid] = 0.0f; }
        __syncthreads();
    }

    int t = blockIdx.x * BLOCK + tid;
    int n = t / CH;
    int c = (t % CH) * 8;
    bool active = (n < N);

    float r[8];
#pragma unroll
    for (int k = 0; k < 8; k++) r[k] = 0.0f;

    if (active) {
        int beg = g_rowstart[n];
        int end = g_rowstart[n + 1];
        float2 a0 = make_float2(0.f, 0.f), a1 = a0, a2 = a0, a3 = a0;
#pragma unroll 2
        for (int j = beg; j < end; j++) {
            int s = __ldg(&g_esrc[j]);
            uint4 v = *reinterpret_cast<const uint4*>(ylh + (size_t)s * COUT + c);
            float2 f0 = __half22float2(*reinterpret_cast<__half2*>(&v.x));
            float2 f1 = __half22float2(*reinterpret_cast<__half2*>(&v.y));
            float2 f2 = __half22float2(*reinterpret_cast<__half2*>(&v.z));
            float2 f3 = __half22float2(*reinterpret_cast<__half2*>(&v.w));
            a0.x += f0.x; a0.y += f0.y;
            a1.x += f1.x; a1.y += f1.y;
            a2.x += f2.x; a2.y += f2.y;
            a3.x += f3.x; a3.y += f3.y;
        }
        float inv = g_inv[n];
        float4 b0 = *reinterpret_cast<const float4*>(yrr + (size_t)n * COUT + c);
        float4 b1 = *reinterpret_cast<const float4*>(yrr + (size_t)n * COUT + c + 4);
        r[0] = fmaf(a0.x, inv, b0.x);
        r[1] = fmaf(a0.y, inv, b0.y);
        r[2] = fmaf(a1.x, inv, b0.z);
        r[3] = fmaf(a1.y, inv, b0.w);
        r[4] = fmaf(a2.x, inv, b1.x);
        r[5] = fmaf(a2.y, inv, b1.y);
        r[6] = fmaf(a3.x, inv, b1.z);
        r[7] = fmaf(a3.y, inv, b1.w);
        *reinterpret_cast<float4*>(out + (size_t)n * COUT + c) =
            make_float4(r[0], r[1], r[2], r[3]);
        *reinterpret_cast<float4*>(out + (size_t)n * COUT + c + 4) =
            make_float4(r[4], r[5], r[6], r[7]);
    }

    if (STATS) {
        // CH == 8 here: lanes l, l+8, l+16, l+24 hold the same channel chunk.
        int lane = tid & 31;
#pragma unroll
        for (int k = 0; k < 8; k++) {
            float v = r[k];
            float q = r[k] * r[k];
            v += __shfl_xor_sync(0xFFFFFFFFu, v, 8);
            q += __shfl_xor_sync(0xFFFFFFFFu, q, 8);
            v += __shfl_xor_sync(0xFFFFFFFFu, v, 16);
            q += __shfl_xor_sync(0xFFFFFFFFu, q, 16);
            if (lane < 8) {
                atomicAdd(&sSum[c + k], v);
                atomicAdd(&sSq[c + k],  q);
            }
        }
        __syncthreads();
        if (tid < 64) {
            atomicAdd(&stats[tid],      sSum[tid]);
            atomicAdd(&stats[64 + tid], sSq[tid]);
        }
        // last-block BN finalize
        if (tid == 0) {
            __threadfence();
            int v = atomicAdd(arrive, 1);
            sLast = (v == (int)gridDim.x - 1);
        }
        __syncthreads();
        if (sLast) {
            __threadfence();
            if (tid < 64) {
                float mu  = stats[tid] * invN;
                float var = stats[64 + tid] * invN - mu * mu;
                float a = gamma[tid] * rsqrtf(var + 1e-5f);
                aff[tid] = a;
                aff[64 + tid] = beta[tid] - mu * a;
            }
        }
    }
}

// ---------------- launch ----------------
extern "C" void kernel_launch(void* const* d_in, const int* in_sizes, int n_in,
                              void* d_out, int out_size) {
    const float* x   = (const float*)d_in[0];
    const void*  ei  = d_in[1];
    const float* Wl0 = (const float*)d_in[2];
    const float* Wr0 = (const float*)d_in[3];
    const float* b0  = (const float*)d_in[4];
    const float* Wl1 = (const float*)d_in[5];
    const float* Wr1 = (const float*)d_in[6];
    const float* b1  = (const float*)d_in[7];
    const float* Wl2 = (const float*)d_in[8];
    const float* Wr2 = (const float*)d_in[9];
    const float* b2  = (const float*)d_in[10];
    const float* g0  = (const float*)d_in[11];
    const float* be0 = (const float*)d_in[12];
    const float* g1  = (const float*)d_in[13];
    const float* be1 = (const float*)d_in[14];
    float* out = (float*)d_out;

    int N = in_sizes[0] / 64;
    int E = in_sizes[1] / 2;
    float invN = 1.0f / (float)N;

    __half* ylhp;
    float *yrp, *h0p, *h1p, *aff0p, *aff1p, *st0p, *st1p;
    int *ar0p, *ar1p;
    cudaGetSymbolAddress((void**)&ylhp, g_ylh);
    cudaGetSymbolAddress((void**)&yrp, g_yr);
    cudaGetSymbolAddress((void**)&h0p, g_h0);
    cudaGetSymbolAddress((void**)&h1p, g_h1);
    cudaGetSymbolAddress((void**)&aff0p, g_aff0);
    cudaGetSymbolAddress((void**)&aff1p, g_aff1);
    cudaGetSymbolAddress((void**)&st0p, g_stats0);
    cudaGetSymbolAddress((void**)&st1p, g_stats1);
    cudaGetSymbolAddress((void**)&ar0p, g_arr0);
    cudaGetSymbolAddress((void**)&ar1p, g_arr1);

    const int smem64 = (64 * (CIN + 4) + CIN * 128) * 4;
    const int smem40 = (64 * (CIN + 4) + CIN * 80) * 4;
    cudaFuncSetAttribute(k_lin<64, false>,
                         cudaFuncAttributeMaxDynamicSharedMemorySize, smem64);
    cudaFuncSetAttribute(k_lin<64, true>,
                         cudaFuncAttributeMaxDynamicSharedMemorySize, smem64);
    cudaFuncSetAttribute(k_lin<40, true>,
                         cudaFuncAttributeMaxDynamicSharedMemorySize, smem40);

    // side stream + events, created once on the (uncaptured) correctness call;
    // host-side objects only — no device memory involved. Same launches every call.
    static cudaStream_t s2 = nullptr;
    static cudaEvent_t evFork = nullptr, evJoin = nullptr;
    if (s2 == nullptr) {
        cudaStreamCreateWithFlags(&s2, cudaStreamNonBlocking);
        cudaEventCreateWithFlags(&evFork, cudaEventDisableTiming);
        cudaEventCreateWithFlags(&evJoin, cudaEventDisableTiming);
    }

    const int nodeBlocks  = (N + 255) / 256;
    const int nodeBlocks1 = (N + 256) / 256;
    const int edgeBlocks  = (E + 255) / 256;
    const int NB          = (N + 255) / 256;
    const int agg64Blocks = (N * 8 + 255) / 256;
    const int agg40Blocks = (N * 5 + 319) / 320;
    const int mmGrid      = (N + 63) / 64;

    // ---- fork: lin0 + stats/counter zero run concurrently with the CSR build ----
    cudaEventRecord(evFork, 0);
    cudaStreamWaitEvent(s2, evFork, 0);
    k_lin<64, false><<<mmGrid, 256, smem64, s2>>>(x, nullptr, Wl0, Wr0, b0,
                                                  ylhp, yrp, N);
    k_zero_stats2<<<1, 128, 0, s2>>>();
    cudaEventRecord(evJoin, s2);

    // ---- main stream: CSR build ----
    k_detect<<<1, 1024>>>((const unsigned int*)ei);
    k_zero_cnt<<<nodeBlocks, 256>>>(N);
    k_decode<<<edgeBlocks, 256>>>(ei, E);
    k_scan1<<<NB, 256>>>(N);
    k_scan2<<<1, 512>>>(NB);
    k_scan3<<<nodeBlocks1, 256>>>(N, E);
    k_fill<<<edgeBlocks, 256>>>(E);

    // ---- join, then the serial layer pipeline ----
    cudaStreamWaitEvent(0, evJoin, 0);

    // layer 0 (agg's last block computes aff0)
    k_agg<64, true, 256><<<agg64Blocks, 256>>>(ylhp, yrp, h0p, st0p, ar0p,
                                               g0, be0, aff0p, invN, N);

    // layer 1
    k_lin<64, true><<<mmGrid, 256, smem64>>>(h0p, aff0p, Wl1, Wr1, b1, ylhp, yrp, N);
    k_agg<64, true, 256><<<agg64Blocks, 256>>>(ylhp, yrp, h1p, st1p, ar1p,
                                               g1, be1, aff1p, invN, N);

    // layer 2
    k_lin<40, true><<<mmGrid, 160, smem40>>>(h1p, aff1p, Wl2, Wr2, b2, ylhp, yrp, N);
    k_agg<40, false, 320><<<agg40Blocks, 320>>>(ylhp, yrp, out, nullptr, nullptr,
                                                nullptr, nullptr, nullptr, 0.f, N);
}

// round 12
// speedup vs baseline: 1.4352x; 1.1269x over previous
#include <cuda_runtime.h>
#include <cuda_fp16.h>
#include <mma.h>
#include <math.h>

using namespace nvcuda;

#define NMAX 100000
#define EMAX 1600000
#define CIN  64

// ---------------- device scratch (no allocation allowed) ----------------
__device__ int   g_is64;
__device__ int   g_src[EMAX];
__device__ int   g_dstE[EMAX];
__device__ int   g_esrc[EMAX];          // CSR: src ids sorted by dst
__device__ int   g_cnt[NMAX];
__device__ int   g_scan[NMAX];
__device__ int   g_bsum[512];
__device__ int   g_boff[512];
__device__ int   g_rowstart[NMAX + 1];
__device__ int   g_cur[NMAX];
__device__ float g_inv[NMAX];
__device__ __align__(256) __half g_ylh[(size_t)NMAX * 64];   // fp16 gather payload
__device__ __align__(256) float  g_yr[(size_t)NMAX * 64];
__device__ __align__(256) float  g_h0[(size_t)NMAX * 64];
__device__ __align__(256) float  g_h1[(size_t)NMAX * 64];
__device__ float g_stats0[128];         // layer0 [sum(64) | sumsq(64)]
__device__ float g_stats1[128];         // layer1
__device__ int   g_arr0;                // arrival counters (last-block bn finalize)
__device__ int   g_arr1;
__device__ float g_aff0[128];           // [scale | shift]
__device__ float g_aff1[128];

// ---------------- dtype detection (int64 vs int32 edge_index) ----------------
__global__ void k_detect(const unsigned int* __restrict__ w) {
    int i = threadIdx.x;
    int ok = (w[2 * i + 1] == 0u) && (w[2 * (i + 1024) + 1] == 0u);
    int all = __syncthreads_and(ok);
    if (i == 0) g_is64 = all ? 1 : 0;
}

__global__ void k_zero_cnt(int N) {
    int i = blockIdx.x * blockDim.x + threadIdx.x;
    if (i < N) g_cnt[i] = 0;
}

__global__ void k_zero_stats2() {
    int i = threadIdx.x;
    if (i < 128) { g_stats0[i] = 0.0f; g_stats1[i] = 0.0f; }
    if (i == 0) { g_arr0 = 0; g_arr1 = 0; }
}

__global__ void k_decode(const void* __restrict__ ei, int E) {
    int i = blockIdx.x * blockDim.x + threadIdx.x;
    if (i >= E) return;
    int s, d;
    if (g_is64) {
        const long long* p = (const long long*)ei;
        s = (int)p[i];
        d = (int)p[E + i];
    } else {
        const int* p = (const int*)ei;
        s = p[i];
        d = p[E + i];
    }
    g_src[i] = s;
    g_dstE[i] = d;
    atomicAdd(&g_cnt[d], 1);
}

__global__ void k_scan1(int N) {
    __shared__ int sh[256];
    int i = blockIdx.x * 256 + threadIdx.x;
    int v = (i < N) ? g_cnt[i] : 0;
    sh[threadIdx.x] = v;
    __syncthreads();
    for (int off = 1; off < 256; off <<= 1) {
        int t = (threadIdx.x >= off) ? sh[threadIdx.x - off] : 0;
        __syncthreads();
        sh[threadIdx.x] += t;
        __syncthreads();
    }
    if (i < N) g_scan[i] = sh[threadIdx.x] - v;
    if (threadIdx.x == 255) g_bsum[blockIdx.x] = sh[255];
}

__global__ void k_scan2(int NB) {
    __shared__ int sh[512];
    int i = threadIdx.x;
    int v = (i < NB) ? g_bsum[i] : 0;
    sh[i] = v;
    __syncthreads();
    for (int off = 1; off < 512; off <<= 1) {
        int t = (i >= off) ? sh[i - off] : 0;
        __syncthreads();
        sh[i] += t;
        __syncthreads();
    }
    g_boff[i] = sh[i] - v;
}

__global__ void k_scan3(int N, int E) {
    int i = blockIdx.x * blockDim.x + threadIdx.x;
    if (i < N) {
        int rs = g_scan[i] + g_boff[i >> 8];
        g_rowstart[i] = rs;
        g_cur[i] = rs;
        g_inv[i] = 1.0f / fmaxf((float)g_cnt[i], 1.0f);
    }
    if (i == N) g_rowstart[N] = E;
}

__global__ void k_fill(int E) {
    int i = blockIdx.x * blockDim.x + threadIdx.x;
    if (i >= E) return;
    int d = g_dstE[i];
    int pos = atomicAdd(&g_cur[d], 1);
    g_esrc[pos] = g_src[i];
}

// ---------------- linear (tensor core): ylh = half(f(x)@Wl), yr = f(x)@Wr + b ----
// f = relu(aff-scale/shift) when AFFINE else identity.
// X staged fp16 [64 x 64], combined W=[Wl|Wr] staged fp16 [64 x 2*COUT].
// wmma 16x16x16 fragments, fp32 accumulate; C staged via smem overlay.
template <int COUT, bool AFFINE>
__global__ void __launch_bounds__((2 * COUT / 16) * 32)
k_lin(const float* __restrict__ x,
      const float* __restrict__ aff,
      const float* __restrict__ Wl,
      const float* __restrict__ Wr,
      const float* __restrict__ bias,
      __half* __restrict__ ylh,
      float* __restrict__ yr,
      int N) {
    constexpr int W  = 2 * COUT;        // 128 or 80
    constexpr int NT = 64;              // node tile (rows)
    constexpr int NWARP = W / 16;       // 8 or 5
    constexpr int THREADS = NWARP * 32; // 256 or 160
    constexpr int LDX = 72;             // fp16 A leading dim (mult of 8)
    constexpr int LDW = W;              // fp16 B leading dim (128/80, mult of 8)
    constexpr int LDC = W + 4;          // fp32 C leading dim (mult of 4)

    extern __shared__ char smemraw[];
    __half* sX = (__half*)smemraw;                        // 64*72 halves
    __half* sW = (__half*)(smemraw + NT * LDX * 2);       // 64*W halves
    float*  sC = (float*)smemraw;                         // overlay: 64*LDC floats

    int tid = threadIdx.x;
    int tile = blockIdx.x * NT;

    // stage combined weights as fp16: row k has [Wl row k | Wr row k]
    for (int i = tid; i < CIN * W; i += THREADS) {
        int k = i / W;
        int c = i % W;
        float v = (c < COUT) ? Wl[k * COUT + c] : Wr[k * COUT + (c - COUT)];
        sW[i] = __float2half(v);
    }

    // stage X rows as fp16 (affine+relu fused), zero-pad tail rows
    for (int q = tid; q < NT * (CIN / 4); q += THREADS) {
        int row = q / (CIN / 4);
        int c4  = (q % (CIN / 4)) * 4;
        int n = tile + row;
        float4 xv = make_float4(0.f, 0.f, 0.f, 0.f);
        if (n < N) {
            xv = *reinterpret_cast<const float4*>(x + (size_t)n * CIN + c4);
            if (AFFINE) {
                float4 A = *reinterpret_cast<const float4*>(aff + c4);
                float4 B = *reinterpret_cast<const float4*>(aff + 64 + c4);
                xv.x = fmaxf(fmaf(xv.x, A.x, B.x), 0.f);
                xv.y = fmaxf(fmaf(xv.y, A.y, B.y), 0.f);
                xv.z = fmaxf(fmaf(xv.z, A.z, B.z), 0.f);
                xv.w = fmaxf(fmaf(xv.w, A.w, B.w), 0.f);
            }
        }
        __half2 h0 = __floats2half2_rn(xv.x, xv.y);
        __half2 h1 = __floats2half2_rn(xv.z, xv.w);
        *reinterpret_cast<__half2*>(sX + row * LDX + c4)     = h0;
        *reinterpret_cast<__half2*>(sX + row * LDX + c4 + 2) = h1;
    }
    __syncthreads();

    // compute: warp w owns n-strip [w*16, w*16+16), all 4 m-tiles
    int w = tid / 32;
    int n0 = w * 16;
    wmma::fragment<wmma::accumulator, 16, 16, 16, float> fc[4];
#pragma unroll
    for (int m = 0; m < 4; m++) wmma::fill_fragment(fc[m], 0.0f);

#pragma unroll
    for (int k = 0; k < 4; k++) {
        wmma::fragment<wmma::matrix_b, 16, 16, 16, __half, wmma::row_major> fb;
        wmma::load_matrix_sync(fb, sW + (k * 16) * LDW + n0, LDW);
#pragma unroll
        for (int m = 0; m < 4; m++) {
            wmma::fragment<wmma::matrix_a, 16, 16, 16, __half, wmma::row_major> fa;
            wmma::load_matrix_sync(fa, sX + (m * 16) * LDX + k * 16, LDX);
            wmma::mma_sync(fc[m], fa, fb, fc[m]);
        }
    }

    __syncthreads();    // inputs dead; safe to overlay C
#pragma unroll
    for (int m = 0; m < 4; m++)
        wmma::store_matrix_sync(sC + (m * 16) * LDC + n0, fc[m], LDC,
                                wmma::mem_row_major);
    __syncthreads();

    // epilogue: split C into ylh (cols 0..COUT) and yr (+bias, cols COUT..W)
    for (int q = tid; q < NT * (COUT / 4); q += THREADS) {
        int row = q / (COUT / 4);
        int c4  = (q % (COUT / 4)) * 4;
        int n = tile + row;
        if (n < N) {
            const float* crow = sC + row * LDC;
            float l0 = crow[c4 + 0], l1 = crow[c4 + 1];
            float l2 = crow[c4 + 2], l3 = crow[c4 + 3];
            __half2 p0 = __floats2half2_rn(l0, l1);
            __half2 p1 = __floats2half2_rn(l2, l3);
            *reinterpret_cast<__half2*>(ylh + (size_t)n * COUT + c4)     = p0;
            *reinterpret_cast<__half2*>(ylh + (size_t)n * COUT + c4 + 2) = p1;
            float4 bv = *reinterpret_cast<const float4*>(bias + c4);
            float4 rv;
            rv.x = crow[COUT + c4 + 0] + bv.x;
            rv.y = crow[COUT + c4 + 1] + bv.y;
            rv.z = crow[COUT + c4 + 2] + bv.z;
            rv.w = crow[COUT + c4 + 3] + bv.w;
            *reinterpret_cast<float4*>(yr + (size_t)n * COUT + c4) = rv;
        }
    }
}

// ---------------- CSR gather reduce: out = invdeg * sum ylh[src] + yr ----------------
// (identical to round 11)
template <int COUT, bool STATS, int BLOCK>
__global__ void __launch_bounds__(BLOCK)
k_agg(const __half* __restrict__ ylh,
      const float* __restrict__ yrr,
      float* __restrict__ out,
      float* __restrict__ stats,
      int* __restrict__ arrive,
      const float* __restrict__ gamma,
      const float* __restrict__ beta,
      float* __restrict__ aff,
      float invN,
      int N) {
    constexpr int CH = COUT / 8;

    __shared__ float sSum[64];
    __shared__ float sSq[64];
    __shared__ int sLast;
    int tid = threadIdx.x;
    if (STATS) {
        if (tid < 64) { sSum[tid] = 0.0f; sSq[tid] = 0.0f; }
        __syncthreads();
    }

    int t = blockIdx.x * BLOCK + tid;
    int n = t / CH;
    int c = (t % CH) * 8;
    bool active = (n < N);

    float r[8];
#pragma unroll
    for (int k = 0; k < 8; k++) r[k] = 0.0f;

    if (active) {
        int beg = g_rowstart[n];
        int end = g_rowstart[n + 1];
        float2 a0 = make_float2(0.f, 0.f), a1 = a0, a2 = a0, a3 = a0;
#pragma unroll 2
        for (int j = beg; j < end; j++) {
            int s = __ldg(&g_esrc[j]);
            uint4 v = *reinterpret_cast<const uint4*>(ylh + (size_t)s * COUT + c);
            float2 f0 = __half22float2(*reinterpret_cast<__half2*>(&v.x));
            float2 f1 = __half22float2(*reinterpret_cast<__half2*>(&v.y));
            float2 f2 = __half22float2(*reinterpret_cast<__half2*>(&v.z));
            float2 f3 = __half22float2(*reinterpret_cast<__half2*>(&v.w));
            a0.x += f0.x; a0.y += f0.y;
            a1.x += f1.x; a1.y += f1.y;
            a2.x += f2.x; a2.y += f2.y;
            a3.x += f3.x; a3.y += f3.y;
        }
        float inv = g_inv[n];
        float4 b0 = *reinterpret_cast<const float4*>(yrr + (size_t)n * COUT + c);
        float4 b1 = *reinterpret_cast<const float4*>(yrr + (size_t)n * COUT + c + 4);
        r[0] = fmaf(a0.x, inv, b0.x);
        r[1] = fmaf(a0.y, inv, b0.y);
        r[2] = fmaf(a1.x, inv, b0.z);
        r[3] = fmaf(a1.y, inv, b0.w);
        r[4] = fmaf(a2.x, inv, b1.x);
        r[5] = fmaf(a2.y, inv, b1.y);
        r[6] = fmaf(a3.x, inv, b1.z);
        r[7] = fmaf(a3.y, inv, b1.w);
        *reinterpret_cast<float4*>(out + (size_t)n * COUT + c) =
            make_float4(r[0], r[1], r[2], r[3]);
        *reinterpret_cast<float4*>(out + (size_t)n * COUT + c + 4) =
            make_float4(r[4], r[5], r[6], r[7]);
    }

    if (STATS) {
        int lane = tid & 31;
#pragma unroll
        for (int k = 0; k < 8; k++) {
            float v = r[k];
            float q = r[k] * r[k];
            v += __shfl_xor_sync(0xFFFFFFFFu, v, 8);
            q += __shfl_xor_sync(0xFFFFFFFFu, q, 8);
            v += __shfl_xor_sync(0xFFFFFFFFu, v, 16);
            q += __shfl_xor_sync(0xFFFFFFFFu, q, 16);
            if (lane < 8) {
                atomicAdd(&sSum[c + k], v);
                atomicAdd(&sSq[c + k],  q);
            }
        }
        __syncthreads();
        if (tid < 64) {
            atomicAdd(&stats[tid],      sSum[tid]);
            atomicAdd(&stats[64 + tid], sSq[tid]);
        }
        if (tid == 0) {
            __threadfence();
            int v = atomicAdd(arrive, 1);
            sLast = (v == (int)gridDim.x - 1);
        }
        __syncthreads();
        if (sLast) {
            __threadfence();
            if (tid < 64) {
                float mu  = stats[tid] * invN;
                float var = stats[64 + tid] * invN - mu * mu;
                float a = gamma[tid] * rsqrtf(var + 1e-5f);
                aff[tid] = a;
                aff[64 + tid] = beta[tid] - mu * a;
            }
        }
    }
}

// ---------------- launch ----------------
extern "C" void kernel_launch(void* const* d_in, const int* in_sizes, int n_in,
                              void* d_out, int out_size) {
    const float* x   = (const float*)d_in[0];
    const void*  ei  = d_in[1];
    const float* Wl0 = (const float*)d_in[2];
    const float* Wr0 = (const float*)d_in[3];
    const float* b0  = (const float*)d_in[4];
    const float* Wl1 = (const float*)d_in[5];
    const float* Wr1 = (const float*)d_in[6];
    const float* b1  = (const float*)d_in[7];
    const float* Wl2 = (const float*)d_in[8];
    const float* Wr2 = (const float*)d_in[9];
    const float* b2  = (const float*)d_in[10];
    const float* g0  = (const float*)d_in[11];
    const float* be0 = (const float*)d_in[12];
    const float* g1  = (const float*)d_in[13];
    const float* be1 = (const float*)d_in[14];
    float* out = (float*)d_out;

    int N = in_sizes[0] / 64;
    int E = in_sizes[1] / 2;
    float invN = 1.0f / (float)N;

    __half* ylhp;
    float *yrp, *h0p, *h1p, *aff0p, *aff1p, *st0p, *st1p;
    int *ar0p, *ar1p;
    cudaGetSymbolAddress((void**)&ylhp, g_ylh);
    cudaGetSymbolAddress((void**)&yrp, g_yr);
    cudaGetSymbolAddress((void**)&h0p, g_h0);
    cudaGetSymbolAddress((void**)&h1p, g_h1);
    cudaGetSymbolAddress((void**)&aff0p, g_aff0);
    cudaGetSymbolAddress((void**)&aff1p, g_aff1);
    cudaGetSymbolAddress((void**)&st0p, g_stats0);
    cudaGetSymbolAddress((void**)&st1p, g_stats1);
    cudaGetSymbolAddress((void**)&ar0p, g_arr0);
    cudaGetSymbolAddress((void**)&ar1p, g_arr1);

    // smem: max(load phase, C overlay phase)
    const int smem64 = 64 * (128 + 4) * 4;          // 33792
    const int smem40 = 64 * (80 + 4) * 4;           // 21504
    cudaFuncSetAttribute(k_lin<64, false>,
                         cudaFuncAttributeMaxDynamicSharedMemorySize, smem64);
    cudaFuncSetAttribute(k_lin<64, true>,
                         cudaFuncAttributeMaxDynamicSharedMemorySize, smem64);
    cudaFuncSetAttribute(k_lin<40, true>,
                         cudaFuncAttributeMaxDynamicSharedMemorySize, smem40);

    static cudaStream_t s2 = nullptr;
    static cudaEvent_t evFork = nullptr, evJoin = nullptr;
    if (s2 == nullptr) {
        cudaStreamCreateWithFlags(&s2, cudaStreamNonBlocking);
        cudaEventCreateWithFlags(&evFork, cudaEventDisableTiming);
        cudaEventCreateWithFlags(&evJoin, cudaEventDisableTiming);
    }

    const int nodeBlocks  = (N + 255) / 256;
    const int nodeBlocks1 = (N + 256) / 256;
    const int edgeBlocks  = (E + 255) / 256;
    const int NB          = (N + 255) / 256;
    const int agg64Blocks = (N * 8 + 255) / 256;
    const int agg40Blocks = (N * 5 + 319) / 320;
    const int mmGrid      = (N + 63) / 64;

    // ---- fork: lin0 + stats/counter zero run concurrently with the CSR build ----
    cudaEventRecord(evFork, 0);
    cudaStreamWaitEvent(s2, evFork, 0);
    k_lin<64, false><<<mmGrid, 256, smem64, s2>>>(x, nullptr, Wl0, Wr0, b0,
                                                  ylhp, yrp, N);
    k_zero_stats2<<<1, 128, 0, s2>>>();
    cudaEventRecord(evJoin, s2);

    // ---- main stream: CSR build ----
    k_detect<<<1, 1024>>>((const unsigned int*)ei);
    k_zero_cnt<<<nodeBlocks, 256>>>(N);
    k_decode<<<edgeBlocks, 256>>>(ei, E);
    k_scan1<<<NB, 256>>>(N);
    k_scan2<<<1, 512>>>(NB);
    k_scan3<<<nodeBlocks1, 256>>>(N, E);
    k_fill<<<edgeBlocks, 256>>>(E);

    // ---- join, then the serial layer pipeline ----
    cudaStreamWaitEvent(0, evJoin, 0);

    // layer 0 (agg's last block computes aff0)
    k_agg<64, true, 256><<<agg64Blocks, 256>>>(ylhp, yrp, h0p, st0p, ar0p,
                                               g0, be0, aff0p, invN, N);

    // layer 1
    k_lin<64, true><<<mmGrid, 256, smem64>>>(h0p, aff0p, Wl1, Wr1, b1, ylhp, yrp, N);
    k_agg<64, true, 256><<<agg64Blocks, 256>>>(ylhp, yrp, h1p, st1p, ar1p,
                                               g1, be1, aff1p, invN, N);

    // layer 2
    k_lin<40, true><<<mmGrid, 160, smem40>>>(h1p, aff1p, Wl2, Wr2, b2, ylhp, yrp, N);
    k_agg<40, false, 320><<<agg40Blocks, 320>>>(ylhp, yrp, out, nullptr, nullptr,
                                                nullptr, nullptr, nullptr, 0.f, N);
}